// round 5
// baseline (speedup 1.0000x reference)
#include <cuda_runtime.h>

// Problem dims (fixed by the dataset)
#define Bn 8
#define Cn 19
#define Hn 384
#define Wn 384
#define NPIX (Bn * Hn * Wn)
#define HWn (Hn * Wn)
#define BOUND 777  // B + C + H + W = 8+1+384+384
#define DT_BLOCKS (12 * 12 * 8)

// Scratch (allocation-free rule: __device__ globals), 16B-aligned for uint4 IO
__device__ __align__(16) unsigned char g_pred[NPIX];
__device__ __align__(16) unsigned char g_tb[NPIX];    // target-border bitmap (0/1)
__device__ float        g_ce;      // zero-init at load; last dt block resets it
__device__ unsigned int g_border;  // ditto
__device__ unsigned int g_cnt;     // ditto

// ---------------------------------------------------------------------------
// Kernel 1: fused CE(sum, ignore=255) + argmax(pred map) + TARGET BORDER map.
// 4 pixels/thread via float4/int4. ONLINE softmax: no 19-wide register array,
// so occupancy is load-latency friendly and the kernel rides the HBM roofline.
// border(i,j) = ((t[i+1,j]-t[i,j]) + (t[i,j+1]-t[i,j])) != 0, zero-padded.
// ---------------------------------------------------------------------------
__global__ void __launch_bounds__(256) ce_kernel(
    const float* __restrict__ x, const int* __restrict__ tgt) {
    int idx4 = blockIdx.x * blockDim.x + threadIdx.x;  // 0 .. NPIX/4-1
    const int HW4 = HWn / 4;
    int b = idx4 / HW4;
    int hw4 = idx4 - b * HW4;
    const float4* p = (const float4*)(x + (size_t)b * Cn * HWn) + hw4;

    int hw = hw4 * 4;
    int i = hw / Wn;                 // row (4 pixels always within one row)
    int j0 = hw - i * Wn;            // col of pixel 0
    int gbase = b * HWn + hw;        // global pixel index of pixel 0

    int4 tq = __ldg((const int4*)tgt + idx4);
    int t[5];
    t[0] = tq.x; t[1] = tq.y; t[2] = tq.z; t[3] = tq.w;
    t[4] = (j0 + 4 < Wn) ? __ldg(tgt + gbase + 4) : t[3];   // row-end pad

    int td[4];
    if (i < Hn - 1) {
        int4 dq = __ldg((const int4*)tgt + idx4 + Wn / 4);
        td[0] = dq.x; td[1] = dq.y; td[2] = dq.z; td[3] = dq.w;
    } else {
        td[0] = t[0]; td[1] = t[1]; td[2] = t[2]; td[3] = t[3];  // bottom pad
    }

    // online softmax state, 4 pixels
    float m[4], s[4], tv[4];
    int arg[4];
    {
        float4 q = __ldg(p);
        float v0[4] = {q.x, q.y, q.z, q.w};
        #pragma unroll
        for (int k = 0; k < 4; k++) {
            m[k] = v0[k]; s[k] = 1.0f; tv[k] = v0[k]; arg[k] = 0;
        }
    }
    #pragma unroll
    for (int c = 1; c < Cn; c++) {
        float4 q = __ldg(p + (size_t)c * HW4);
        float vc[4] = {q.x, q.y, q.z, q.w};
        #pragma unroll
        for (int k = 0; k < 4; k++) {
            float nm = fmaxf(m[k], vc[k]);
            s[k] = s[k] * __expf(m[k] - nm) + __expf(vc[k] - nm);
            if (vc[k] > m[k]) arg[k] = c;        // first-max tie break
            m[k] = nm;
            tv[k] = (c == t[k]) ? vc[k] : tv[k]; // register-resident gather
        }
    }

    float nll = 0.0f;
    unsigned int packed_pred = 0, packed_border = 0;
    #pragma unroll
    for (int k = 0; k < 4; k++) {
        packed_pred |= ((unsigned int)arg[k]) << (8 * k);
        int bd = (((td[k] - t[k]) + (t[k + 1] - t[k])) != 0) ? 1 : 0;
        packed_border |= ((unsigned int)bd) << (8 * k);
        if (t[k] != 255) nll += (m[k] + __logf(s[k])) - tv[k];
    }
    ((unsigned int*)g_pred)[idx4] = packed_pred;
    ((unsigned int*)g_tb)[idx4]   = packed_border;

    // block reduction -> atomicAdd
    #pragma unroll
    for (int o = 16; o > 0; o >>= 1)
        nll += __shfl_down_sync(0xFFFFFFFFu, nll, o);
    __shared__ float ws[8];
    int lane = threadIdx.x & 31, wid = threadIdx.x >> 5;
    if (lane == 0) ws[wid] = nll;
    __syncthreads();
    if (wid == 0) {
        float v2 = (lane < (blockDim.x >> 5)) ? ws[lane] : 0.0f;
        #pragma unroll
        for (int o = 4; o > 0; o >>= 1)
            v2 += __shfl_down_sync(0xFFFFFFFFu, v2, o);
        if (lane == 0) atomicAdd(&g_ce, v2);
    }
}

// ---------------------------------------------------------------------------
// Kernel 2: 2-D Chebyshev distance via expanding-ring search + pred-border
// masking + border-loss reduction. One 32x32 tile per block (32x8 threads,
// 4 rows/thread). Border halo 64x64 in shared; exact global fallback d>=16.
// LAST BLOCK finalizes: out = g_ce + 0.2*border, then resets accumulators
// (self-cleaning -> no init/final kernels, graph-replay idempotent).
// ---------------------------------------------------------------------------
__global__ void __launch_bounds__(256) dt_kernel(float* __restrict__ out) {
    __shared__ unsigned char sB[64 * 64];   // target-border halo
    __shared__ unsigned char sP[34 * 48];   // pred halo (33x33 needed)
    __shared__ int wsum[8];

    int bimg = blockIdx.z;
    int r0 = blockIdx.y * 32, c0 = blockIdx.x * 32;
    int tid = threadIdx.y * 32 + threadIdx.x;
    const unsigned char* tb = g_tb + bimg * HWn;
    const unsigned char* pp = g_pred + bimg * HWn;

    // Load border halo: 64 rows x 4 aligned 16B chunks; OOB chunk -> 0.
    {
        int row = tid >> 2, ch = tid & 3;
        int r = r0 - 16 + row;
        int c = c0 - 16 + ch * 16;           // multiple of 16
        uint4 val = make_uint4(0u, 0u, 0u, 0u);
        if (r >= 0 && r < Hn && c >= 0 && c < Wn)
            val = *(const uint4*)(tb + r * Wn + c);
        *(uint4*)(sB + row * 64 + ch * 16) = val;
    }
    // Load pred halo: 34 rows x 3 aligned 16B chunks; OOB chunk -> 0.
    if (tid < 102) {
        int row = tid / 3, ch = tid - row * 3;
        int r = r0 + row;
        int c = c0 + ch * 16;
        uint4 val = make_uint4(0u, 0u, 0u, 0u);
        if (r < Hn && c < Wn)
            val = *(const uint4*)(pp + r * Wn + c);
        *(uint4*)(sP + row * 48 + ch * 16) = val;
    }
    __syncthreads();

    int contrib = 0;
    #pragma unroll
    for (int k = 0; k < 4; k++) {
        int lr = threadIdx.y + k * 8;        // 0..31
        int lc = threadIdx.x;                // 0..31
        int gi = r0 + lr, gj = c0 + lc;

        // pred border at (gi, gj)
        int p0 = sP[lr * 48 + lc];
        int pr = (gj < Wn - 1) ? sP[lr * 48 + lc + 1]   : p0;
        int pd = (gi < Hn - 1) ? sP[(lr + 1) * 48 + lc] : p0;
        bool pb = (((pd - p0) + (pr - p0)) != 0);

        if (pb) {
            int sr = lr + 16, sc = lc + 16;
            int d;
            if (sB[sr * 64 + sc]) {
                d = 0;
            } else {
                int tt = 1;
                bool f = false;
                for (; tt < 16; tt++) {
                    f = false;
                    int top = (sr - tt) * 64, bot = (sr + tt) * 64;
                    for (int dx = -tt; dx <= tt; dx++)
                        f |= (sB[top + sc + dx] | sB[bot + sc + dx]) != 0;
                    for (int dy = -tt + 1; dy <= tt - 1; dy++) {
                        int rr = (sr + dy) * 64;
                        f |= (sB[rr + sc - tt] | sB[rr + sc + tt]) != 0;
                    }
                    if (f) break;
                }
                if (f) {
                    d = tt;
                } else {
                    // exact global fallback (essentially never taken)
                    d = BOUND;
                    for (; tt <= Hn + Wn; tt++) {
                        bool g = false;
                        int ra = gi - tt, rb = gi + tt;
                        int ca = gj - tt, cb = gj + tt;
                        int cl = ca > 0 ? ca : 0;
                        int cr = cb < Wn - 1 ? cb : Wn - 1;
                        if (ra >= 0) for (int c = cl; c <= cr; c++) g |= tb[ra * Wn + c] != 0;
                        if (rb < Hn) for (int c = cl; c <= cr; c++) g |= tb[rb * Wn + c] != 0;
                        int rl = (ra + 1) > 0 ? (ra + 1) : 0;
                        int rh = (rb - 1) < Hn - 1 ? (rb - 1) : Hn - 1;
                        if (ca >= 0) for (int r = rl; r <= rh; r++) g |= tb[r * Wn + ca] != 0;
                        if (cb < Wn) for (int r = rl; r <= rh; r++) g |= tb[r * Wn + cb] != 0;
                        if (g) { d = tt; break; }
                        if (ra < 0 && rb >= Hn && ca < 0 && cb >= Wn) break;  // whole image scanned
                    }
                }
            }
            contrib += d;
        }
    }

    // integer block reduction (exact) -> u32 atomic
    #pragma unroll
    for (int o = 16; o > 0; o >>= 1)
        contrib += __shfl_down_sync(0xFFFFFFFFu, contrib, o);
    int lane = tid & 31, wid = tid >> 5;
    if (lane == 0) wsum[wid] = contrib;
    __syncthreads();
    if (wid == 0) {
        int v2 = (lane < 8) ? wsum[lane] : 0;
        #pragma unroll
        for (int o = 4; o > 0; o >>= 1)
            v2 += __shfl_down_sync(0xFFFFFFFFu, v2, o);
        if (lane == 0) {
            atomicAdd(&g_border, (unsigned int)v2);
            __threadfence();
            unsigned int done = atomicAdd(&g_cnt, 1u);
            if (done == DT_BLOCKS - 1) {       // last block: finalize + reset
                __threadfence();
                out[0] = g_ce + 0.2f * (float)g_border;
                g_ce = 0.0f;
                g_border = 0u;
                g_cnt = 0u;
            }
        }
    }
}

extern "C" void kernel_launch(void* const* d_in, const int* in_sizes, int n_in,
                              void* d_out, int out_size) {
    const float* slices  = (const float*)d_in[0];
    const int*   targets = (const int*)d_in[1];   // JAX int64 -> int32 (x64 disabled)
    float* out = (float*)d_out;

    ce_kernel<<<(NPIX / 4) / 256, 256>>>(slices, targets);
    dt_kernel<<<dim3(Wn / 32, Hn / 32, Bn), dim3(32, 8)>>>(out);
}

// round 6
// speedup vs baseline: 1.1837x; 1.1837x over previous
#include <cuda_runtime.h>

// Problem dims (fixed by the dataset)
#define Bn 8
#define Cn 19
#define Hn 384
#define Wn 384
#define NPIX (Bn * Hn * Wn)
#define HWn (Hn * Wn)
#define BOUND 777  // B + C + H + W = 8+1+384+384
#define DT_BLOCKS (12 * 12 * 8)

// Scratch (allocation-free rule: __device__ globals), 16B-aligned for uint4 IO
__device__ __align__(16) unsigned char g_pred[NPIX];
__device__ __align__(16) unsigned char g_tb[NPIX];    // target-border bitmap (0/1)
__device__ float        g_ce;      // zero-init at load; last dt block resets it
__device__ unsigned int g_border;  // ditto
__device__ unsigned int g_cnt;     // ditto

// ---------------------------------------------------------------------------
// Kernel 1: fused CE(sum, ignore=255) + argmax(pred map) + TARGET BORDER map.
// 4 pixels/thread via float4/int4; 19 channel float4s in registers (R4 form:
// max pass, then independent exp sum -> no serial MUFU chain).
// border(i,j) = ((t[i+1,j]-t[i,j]) + (t[i,j+1]-t[i,j])) != 0, zero-padded.
// ---------------------------------------------------------------------------
__global__ void __launch_bounds__(256) ce_kernel(
    const float* __restrict__ x, const int* __restrict__ tgt) {
    int idx4 = blockIdx.x * blockDim.x + threadIdx.x;  // 0 .. NPIX/4-1
    const int HW4 = HWn / 4;
    int b = idx4 / HW4;
    int hw4 = idx4 - b * HW4;
    const float4* p = (const float4*)(x + (size_t)b * Cn * HWn) + hw4;

    float v[Cn][4];
    #pragma unroll
    for (int c = 0; c < Cn; c++) {
        float4 q = __ldg(p + (size_t)c * HW4);
        v[c][0] = q.x; v[c][1] = q.y; v[c][2] = q.z; v[c][3] = q.w;
    }

    int hw = hw4 * 4;
    int i = hw / Wn;                 // row (4 pixels always within one row)
    int j0 = hw - i * Wn;            // col of pixel 0
    int gbase = b * HWn + hw;        // global pixel index of pixel 0

    int4 tq = __ldg((const int4*)tgt + idx4);
    int t[5];
    t[0] = tq.x; t[1] = tq.y; t[2] = tq.z; t[3] = tq.w;
    t[4] = (j0 + 4 < Wn) ? __ldg(tgt + gbase + 4) : t[3];   // row-end pad

    int td[4];
    if (i < Hn - 1) {
        int4 dq = __ldg((const int4*)tgt + idx4 + Wn / 4);
        td[0] = dq.x; td[1] = dq.y; td[2] = dq.z; td[3] = dq.w;
    } else {
        td[0] = t[0]; td[1] = t[1]; td[2] = t[2]; td[3] = t[3];  // bottom pad
    }

    float nll = 0.0f;
    unsigned int packed_pred = 0, packed_border = 0;
    #pragma unroll
    for (int k = 0; k < 4; k++) {
        float m = v[0][k];
        int arg = 0;
        float tv = v[0][k];
        #pragma unroll
        for (int c = 1; c < Cn; c++) {
            float vc = v[c][k];
            if (vc > m) { m = vc; arg = c; }     // first-max tie break
            tv = (c == t[k]) ? vc : tv;           // register-resident gather
        }
        packed_pred |= ((unsigned int)arg) << (8 * k);

        int bd = (((td[k] - t[k]) + (t[k + 1] - t[k])) != 0) ? 1 : 0;
        packed_border |= ((unsigned int)bd) << (8 * k);

        float s = 0.0f;
        #pragma unroll
        for (int c = 0; c < Cn; c++) s += __expf(v[c][k] - m);

        if (t[k] != 255) nll += (m + __logf(s)) - tv;
    }
    ((unsigned int*)g_pred)[idx4] = packed_pred;
    ((unsigned int*)g_tb)[idx4]   = packed_border;

    // block reduction -> atomicAdd
    #pragma unroll
    for (int o = 16; o > 0; o >>= 1)
        nll += __shfl_down_sync(0xFFFFFFFFu, nll, o);
    __shared__ float ws[8];
    int lane = threadIdx.x & 31, wid = threadIdx.x >> 5;
    if (lane == 0) ws[wid] = nll;
    __syncthreads();
    if (wid == 0) {
        float v2 = (lane < (blockDim.x >> 5)) ? ws[lane] : 0.0f;
        #pragma unroll
        for (int o = 4; o > 0; o >>= 1)
            v2 += __shfl_down_sync(0xFFFFFFFFu, v2, o);
        if (lane == 0) atomicAdd(&g_ce, v2);
    }
}

// ---------------------------------------------------------------------------
// Kernel 2: border loss. Key fact: d=0 contributes nothing, and ~99.7% of
// pixels have a target border AT the pixel (d=0). Fast path: one u32 LDS
// covers 4 pixels' center border bytes; if all nonzero -> skip entirely.
// Rare path: pred-border test + expanding-ring search (exact global fallback).
// LAST BLOCK finalizes out = g_ce + 0.2*border and resets accumulators.
// ---------------------------------------------------------------------------
__global__ void __launch_bounds__(256) dt_kernel(float* __restrict__ out) {
    __shared__ unsigned char sB[64 * 64];   // target-border halo (16-px apron)
    __shared__ unsigned char sP[34 * 48];   // pred halo (33x33 needed)
    __shared__ int wsum[8];

    int bimg = blockIdx.z;
    int r0 = blockIdx.y * 32, c0 = blockIdx.x * 32;
    int tid = threadIdx.y * 32 + threadIdx.x;
    const unsigned char* tb = g_tb + bimg * HWn;
    const unsigned char* pp = g_pred + bimg * HWn;

    // Load border halo: 64 rows x 4 aligned 16B chunks; OOB chunk -> 0.
    {
        int row = tid >> 2, ch = tid & 3;
        int r = r0 - 16 + row;
        int c = c0 - 16 + ch * 16;           // multiple of 16
        uint4 val = make_uint4(0u, 0u, 0u, 0u);
        if (r >= 0 && r < Hn && c >= 0 && c < Wn)
            val = *(const uint4*)(tb + r * Wn + c);
        *(uint4*)(sB + row * 64 + ch * 16) = val;
    }
    // Load pred halo: 34 rows x 3 aligned 16B chunks; OOB chunk -> 0.
    if (tid < 102) {
        int row = tid / 3, ch = tid - row * 3;
        int r = r0 + row;
        int c = c0 + ch * 16;
        uint4 val = make_uint4(0u, 0u, 0u, 0u);
        if (r < Hn && c < Wn)
            val = *(const uint4*)(pp + r * Wn + c);
        *(uint4*)(sP + row * 48 + ch * 16) = val;
    }
    __syncthreads();

    // Each thread owns 4 horizontally consecutive pixels.
    int lr = tid >> 3;              // row in tile 0..31
    int lc4 = (tid & 7) * 4;        // col base 0,4,...,28
    int sr = lr + 16;

    int contrib = 0;
    unsigned int cw = *(const unsigned int*)(sB + sr * 64 + 16 + lc4);
    if (cw != 0x01010101u) {        // some pixel has no border at center
        #pragma unroll
        for (int k = 0; k < 4; k++) {
            if (((cw >> (8 * k)) & 0xFFu) != 0u) continue;  // d=0 -> adds 0
            int lc = lc4 + k;
            int gi = r0 + lr, gj = c0 + lc;

            // pred border at (gi, gj)
            int p0 = sP[lr * 48 + lc];
            int pr = (gj < Wn - 1) ? sP[lr * 48 + lc + 1]   : p0;
            int pd = (gi < Hn - 1) ? sP[(lr + 1) * 48 + lc] : p0;
            if ((((pd - p0) + (pr - p0)) != 0)) {
                int sc = lc + 16;
                int d;
                int tt = 1;
                bool f = false;
                for (; tt < 16; tt++) {
                    f = false;
                    int top = (sr - tt) * 64, bot = (sr + tt) * 64;
                    for (int dx = -tt; dx <= tt; dx++)
                        f |= (sB[top + sc + dx] | sB[bot + sc + dx]) != 0;
                    for (int dy = -tt + 1; dy <= tt - 1; dy++) {
                        int rr = (sr + dy) * 64;
                        f |= (sB[rr + sc - tt] | sB[rr + sc + tt]) != 0;
                    }
                    if (f) break;
                }
                if (f) {
                    d = tt;
                } else {
                    // exact global fallback (essentially never taken)
                    d = BOUND;
                    for (; tt <= Hn + Wn; tt++) {
                        bool g = false;
                        int ra = gi - tt, rb = gi + tt;
                        int ca = gj - tt, cb = gj + tt;
                        int cl = ca > 0 ? ca : 0;
                        int cr = cb < Wn - 1 ? cb : Wn - 1;
                        if (ra >= 0) for (int c = cl; c <= cr; c++) g |= tb[ra * Wn + c] != 0;
                        if (rb < Hn) for (int c = cl; c <= cr; c++) g |= tb[rb * Wn + c] != 0;
                        int rl = (ra + 1) > 0 ? (ra + 1) : 0;
                        int rh = (rb - 1) < Hn - 1 ? (rb - 1) : Hn - 1;
                        if (ca >= 0) for (int r = rl; r <= rh; r++) g |= tb[r * Wn + ca] != 0;
                        if (cb < Wn) for (int r = rl; r <= rh; r++) g |= tb[r * Wn + cb] != 0;
                        if (g) { d = tt; break; }
                        if (ra < 0 && rb >= Hn && ca < 0 && cb >= Wn) break;
                    }
                }
                contrib += d;
            }
        }
    }

    // integer block reduction (exact) -> u32 atomic
    #pragma unroll
    for (int o = 16; o > 0; o >>= 1)
        contrib += __shfl_down_sync(0xFFFFFFFFu, contrib, o);
    int lane = tid & 31, wid = tid >> 5;
    if (lane == 0) wsum[wid] = contrib;
    __syncthreads();
    if (wid == 0) {
        int v2 = (lane < 8) ? wsum[lane] : 0;
        #pragma unroll
        for (int o = 4; o > 0; o >>= 1)
            v2 += __shfl_down_sync(0xFFFFFFFFu, v2, o);
        if (lane == 0) {
            atomicAdd(&g_border, (unsigned int)v2);
            __threadfence();
            unsigned int done = atomicAdd(&g_cnt, 1u);
            if (done == DT_BLOCKS - 1) {       // last block: finalize + reset
                __threadfence();
                out[0] = g_ce + 0.2f * (float)g_border;
                g_ce = 0.0f;
                g_border = 0u;
                g_cnt = 0u;
            }
        }
    }
}

extern "C" void kernel_launch(void* const* d_in, const int* in_sizes, int n_in,
                              void* d_out, int out_size) {
    const float* slices  = (const float*)d_in[0];
    const int*   targets = (const int*)d_in[1];   // JAX int64 -> int32 (x64 disabled)
    float* out = (float*)d_out;

    ce_kernel<<<(NPIX / 4) / 256, 256>>>(slices, targets);
    dt_kernel<<<dim3(Wn / 32, Hn / 32, Bn), dim3(32, 8)>>>(out);
}